// round 3
// baseline (speedup 1.0000x reference)
#include <cuda_runtime.h>

#define N_NODES   200000
#define N_EDGES   3200000
#define N_GRAPHS  1024

// ---------------- scratch (static device globals) ---------------------------
__device__ float g_S[N_NODES * 64];    // scaled activations S = h * dinv
__device__ float g_U[N_NODES * 64];    // gemm outputs / aggregated t
__device__ float g_xs[N_NODES * 8];    // x * dinv
__device__ int   g_deg[N_NODES];
__device__ int   g_off[N_NODES + 1];   // CSR offsets (incoming edges by dst)
__device__ int   g_cur[N_NODES];       // fill cursors
__device__ int   g_csr[N_EDGES];       // src per slot
__device__ float g_dinv[N_NODES];
__device__ float g_gmax[N_GRAPHS * 32];
__device__ float g_gsum[N_GRAPHS * 32];
__device__ float g_cnt[N_GRAPHS];
__device__ int   g_idx64;

// ---------------- prep kernels ----------------------------------------------

__global__ void detect_kernel(const void* __restrict__ ei) {
    const long long* p = (const long long*)ei;
    int ok = 1;
#pragma unroll
    for (int i = 0; i < 16; i++) {
        long long v = p[i];
        if (v < 0 || v >= N_NODES) ok = 0;
    }
    g_idx64 = ok;
}

__global__ void init_kernel() {
    int i = blockIdx.x * blockDim.x + threadIdx.x;
    if (i < N_NODES) g_deg[i] = 0;
    if (i < N_GRAPHS * 32) { g_gmax[i] = 0.0f; g_gsum[i] = 0.0f; }
    if (i < N_GRAPHS) g_cnt[i] = 0.0f;
}

__global__ void deg_kernel(const void* __restrict__ ei) {
    int e = blockIdx.x * blockDim.x + threadIdx.x;
    if (e >= N_EDGES) return;
    int d;
    if (g_idx64) d = (int)((const long long*)ei)[N_EDGES + e];
    else         d = ((const int*)ei)[N_EDGES + e];
    atomicAdd(&g_deg[d], 1);
}

// Single-block scan: offsets, cursors, dinv (deg incl. self-loop).
__global__ void scan_kernel() {
    __shared__ int part[1024];
    const int tid = threadIdx.x;
    const int CH = (N_NODES + 1023) / 1024;   // 196
    const int base = tid * CH;
    int mysum = 0;
    for (int i = 0; i < CH; i++) {
        int idx = base + i;
        if (idx < N_NODES) mysum += g_deg[idx];
    }
    part[tid] = mysum;
    __syncthreads();
    for (int off = 1; off < 1024; off <<= 1) {
        int v = (tid >= off) ? part[tid - off] : 0;
        __syncthreads();
        part[tid] += v;
        __syncthreads();
    }
    int run = part[tid] - mysum;   // exclusive prefix
    for (int i = 0; i < CH; i++) {
        int idx = base + i;
        if (idx < N_NODES) {
            g_off[idx] = run;
            g_cur[idx] = run;
            int dg = g_deg[idx];
            g_dinv[idx] = rsqrtf((float)(dg + 1));
            run += dg;
        }
    }
    if (tid == 1023) g_off[N_NODES] = part[1023];
}

__global__ void fill_kernel(const void* __restrict__ ei) {
    int e = blockIdx.x * blockDim.x + threadIdx.x;
    if (e >= N_EDGES) return;
    int s, d;
    if (g_idx64) {
        const long long* p = (const long long*)ei;
        s = (int)p[e]; d = (int)p[N_EDGES + e];
    } else {
        const int* p = (const int*)ei;
        s = p[e]; d = p[N_EDGES + e];
    }
    int pos = atomicAdd(&g_cur[d], 1);
    g_csr[pos] = s;
}

// xs = x * dinv  (width 8, float4 granularity: 2 threads/node)
__global__ void xscale_kernel(const float* __restrict__ x) {
    int t = blockIdx.x * blockDim.x + threadIdx.x;
    if (t >= N_NODES * 2) return;
    int node = t >> 1;
    float dv = g_dinv[node];
    float4 v = *(const float4*)(x + (size_t)t * 4);
    v.x *= dv; v.y *= dv; v.z *= dv; v.w *= dv;
    *(float4*)(g_xs + (size_t)t * 4) = v;
}

// ---------------- layer kernels ---------------------------------------------

// Width-8 input aggregation: t0[d] = dinv[d] * (sum_s xs[s] + xs[d]).
// 8 threads per node, scalar floats (one 32B sector per edge).
__global__ void agg0_kernel() {
    int gid = blockIdx.x * blockDim.x + threadIdx.x;
    int node = gid >> 3;
    int lane = gid & 7;
    if (node >= N_NODES) return;
    float acc0 = g_xs[(size_t)node * 8 + lane];
    float acc1 = 0.0f;
    int e = g_off[node], e1 = g_off[node + 1];
    for (; e + 2 <= e1; e += 2) {
        int s0 = __ldg(&g_csr[e]);
        int s1 = __ldg(&g_csr[e + 1]);
        acc0 += __ldg(&g_xs[(size_t)s0 * 8 + lane]);
        acc1 += __ldg(&g_xs[(size_t)s1 * 8 + lane]);
    }
    if (e < e1) {
        int s0 = __ldg(&g_csr[e]);
        acc0 += __ldg(&g_xs[(size_t)s0 * 8 + lane]);
    }
    g_U[(size_t)node * 8 + lane] = (acc0 + acc1) * g_dinv[node];
}

// GEMM: out = in @ W  (optionally epilogue: tanh(.+b)*dinv for layer 0)
// EPI: 0 = none, 1 = tanh(+b)*dinv
template <int K, int NO, int EPI>
__global__ void gemm_kernel(const float* __restrict__ in, const float* __restrict__ W,
                            const float* __restrict__ b, float* __restrict__ out) {
    const int TPN = NO / 4;
    const int NPB = 256 / TPN;
    __shared__ float sW[K * NO];
    __shared__ float sIn[NPB * K];
    for (int i = threadIdx.x; i < K * NO; i += 256) sW[i] = W[i];
    int node0 = blockIdx.x * NPB;
    for (int i = threadIdx.x; i < NPB * K; i += 256) {
        int n = node0 + i / K;
        sIn[i] = (n < N_NODES) ? in[(size_t)n * K + (i % K)] : 0.0f;
    }
    __syncthreads();
    int node = node0 + threadIdx.x / TPN;
    int oc   = (threadIdx.x % TPN) * 4;
    if (node >= N_NODES) return;
    const float* r = sIn + (threadIdx.x / TPN) * K;
    float a0 = 0.f, a1 = 0.f, a2 = 0.f, a3 = 0.f;
#pragma unroll
    for (int k = 0; k < K; k++) {
        float xv = r[k];
        float4 w = *(const float4*)(sW + k * NO + oc);
        a0 += xv * w.x; a1 += xv * w.y; a2 += xv * w.z; a3 += xv * w.w;
    }
    float4 res;
    if (EPI == 1) {
        float dv = g_dinv[node];
        float4 bb = *(const float4*)(b + oc);
        res.x = tanhf(a0 + bb.x) * dv;
        res.y = tanhf(a1 + bb.y) * dv;
        res.z = tanhf(a2 + bb.z) * dv;
        res.w = tanhf(a3 + bb.w) * dv;
    } else {
        res = make_float4(a0, a1, a2, a3);
    }
    *(float4*)(out + (size_t)node * NO + oc) = res;
}

// Aggregation in output space + epilogue.
// out_next = relu(dinv*(sum u[s] + u[d]) + b)  [* dinv if !POOL]
// 16 threads/node, V = NO/16 floats per thread (4 for NO=64, 2 for NO=32).
template <int NO, bool POOL>
__global__ void agg_act_kernel(const float* __restrict__ u, const float* __restrict__ b,
                               float* __restrict__ out, const void* __restrict__ batch) {
    const int V = NO / 16;
    int gid  = blockIdx.x * blockDim.x + threadIdx.x;
    int node = gid >> 4;
    int lane = gid & 15;
    if (node >= N_NODES) return;
    const float* urow = u + (size_t)node * NO + lane * V;
    float acc0[V], acc1[V];
#pragma unroll
    for (int j = 0; j < V; j++) { acc0[j] = urow[j]; acc1[j] = 0.0f; }
    int e = g_off[node], e1 = g_off[node + 1];
    for (; e + 2 <= e1; e += 2) {
        int s0 = __ldg(&g_csr[e]);
        int s1 = __ldg(&g_csr[e + 1]);
        const float* p0 = u + (size_t)s0 * NO + lane * V;
        const float* p1 = u + (size_t)s1 * NO + lane * V;
#pragma unroll
        for (int j = 0; j < V; j++) { acc0[j] += __ldg(p0 + j); acc1[j] += __ldg(p1 + j); }
    }
    if (e < e1) {
        int s0 = __ldg(&g_csr[e]);
        const float* p0 = u + (size_t)s0 * NO + lane * V;
#pragma unroll
        for (int j = 0; j < V; j++) acc0[j] += __ldg(p0 + j);
    }
    float dv = g_dinv[node];
    float val[V];
#pragma unroll
    for (int j = 0; j < V; j++)
        val[j] = fmaxf(fmaf(dv, acc0[j] + acc1[j], b[lane * V + j]), 0.0f);
    if (!POOL) {
#pragma unroll
        for (int j = 0; j < V; j++)
            out[(size_t)node * NO + lane * V + j] = val[j] * dv;
    } else {
        int g;
        if (g_idx64) g = (int)((const long long*)batch)[node];
        else         g = ((const int*)batch)[node];
        int base = g * 32 + lane * V;
#pragma unroll
        for (int j = 0; j < V; j++) {
            atomicMax((int*)&g_gmax[base + j], __float_as_int(val[j]));
            atomicAdd(&g_gsum[base + j], val[j]);
        }
        if (lane == 0) atomicAdd(&g_cnt[g], 1.0f);
    }
}

__global__ void final_kernel(const float* __restrict__ Wout, const float* __restrict__ bout,
                             float* __restrict__ out) {
    int idx = blockIdx.x * blockDim.x + threadIdx.x;
    if (idx >= N_GRAPHS * 10) return;
    int g = idx / 10, o = idx % 10;
    float inv = 1.0f / fmaxf(g_cnt[g], 1.0f);
    float s = bout[o];
#pragma unroll
    for (int f = 0; f < 32; f++) s = fmaf(g_gmax[g * 32 + f], Wout[f * 10 + o], s);
#pragma unroll
    for (int f = 0; f < 32; f++) s = fmaf(g_gsum[g * 32 + f] * inv, Wout[(32 + f) * 10 + o], s);
    out[idx] = s;
}

// ---------------- launch -----------------------------------------------------

extern "C" void kernel_launch(void* const* d_in, const int* in_sizes, int n_in,
                              void* d_out, int out_size) {
    const float* x     = (const float*)d_in[0];
    const void*  ei    = d_in[1];
    const void*  batch = d_in[2];
    const float* W0 = (const float*)d_in[3];  const float* b0 = (const float*)d_in[4];
    const float* W1 = (const float*)d_in[5];  const float* b1 = (const float*)d_in[6];
    const float* W2 = (const float*)d_in[7];  const float* b2 = (const float*)d_in[8];
    const float* W3 = (const float*)d_in[9];  const float* b3 = (const float*)d_in[10];
    const float* Wout = (const float*)d_in[11];
    const float* bout = (const float*)d_in[12];
    float* out = (float*)d_out;

    float *S, *U;
    cudaGetSymbolAddress((void**)&S, g_S);
    cudaGetSymbolAddress((void**)&U, g_U);

    const int T = 256;
    const int NB_N  = (N_NODES + T - 1) / T;
    const int NB_E  = (N_EDGES + T - 1) / T;
    const int NB_N2 = (N_NODES * 2 + T - 1) / T;
    const int NB_N8 = (N_NODES * 8 + T - 1) / T;
    const int NB_N16 = (N_NODES * 16 + T - 1) / T;

    // graph prep
    detect_kernel<<<1, 1>>>(ei);
    init_kernel<<<NB_N, T>>>();
    deg_kernel<<<NB_E, T>>>(ei);
    scan_kernel<<<1, 1024>>>();
    fill_kernel<<<NB_E, T>>>(ei);

    // Layer 0 (8 -> 64, tanh): aggregate in input space (width 8), then GEMM+act.
    xscale_kernel<<<NB_N2, T>>>(x);
    agg0_kernel<<<NB_N8, T>>>();
    gemm_kernel<8, 64, 1><<<(N_NODES + 15) / 16, T>>>(U, W0, b0, S);

    // Layer 1 (64 -> 64, relu): GEMM then aggregate (width 64).
    gemm_kernel<64, 64, 0><<<(N_NODES + 15) / 16, T>>>(S, W1, nullptr, U);
    agg_act_kernel<64, false><<<NB_N16, T>>>(U, b1, S, nullptr);

    // Layer 2 (64 -> 32, relu): GEMM then aggregate (width 32).
    gemm_kernel<64, 32, 0><<<(N_NODES + 31) / 32, T>>>(S, W2, nullptr, U);
    agg_act_kernel<32, false><<<NB_N16, T>>>(U, b2, S, nullptr);

    // Layer 3 (32 -> 32, relu): GEMM then aggregate + fused pooling.
    gemm_kernel<32, 32, 0><<<(N_NODES + 31) / 32, T>>>(S, W3, nullptr, U);
    agg_act_kernel<32, true><<<NB_N16, T>>>(U, b3, nullptr, batch);

    final_kernel<<<(N_GRAPHS * 10 + T - 1) / T, T>>>(Wout, bout, out);
}

// round 5
// speedup vs baseline: 1.6986x; 1.6986x over previous
#include <cuda_runtime.h>

#define N_NODES   200000
#define N_EDGES   3200000
#define N_GRAPHS  1024

#define SCAN_CHUNK 2048
#define SCAN_NBLK  ((N_NODES + SCAN_CHUNK - 1) / SCAN_CHUNK)   // 98

// ---------------- scratch (static device globals) ---------------------------
__device__ float g_S[N_NODES * 64];    // scaled activations S = h * dinv
__device__ float g_U[N_NODES * 64];    // gemm outputs / aggregated t
__device__ float g_xs[N_NODES * 8];    // x * dinv
__device__ int   g_deg[N_NODES];
__device__ int   g_off[N_NODES + 1];   // CSR offsets (incoming edges by dst)
__device__ int   g_cur[N_NODES];       // fill cursors
__device__ int   g_csr[N_EDGES];       // src per slot
__device__ float g_dinv[N_NODES];
__device__ int   g_blksum[SCAN_NBLK];
__device__ int   g_blkoff[SCAN_NBLK];
__device__ float g_gmax[N_GRAPHS * 32];
__device__ float g_gsum[N_GRAPHS * 32];
__device__ float g_cnt[N_GRAPHS];
__device__ int   g_idx64;

// ---------------- prep kernels ----------------------------------------------

__global__ void detect_kernel(const void* __restrict__ ei) {
    const long long* p = (const long long*)ei;
    int ok = 1;
#pragma unroll
    for (int i = 0; i < 16; i++) {
        long long v = p[i];
        if (v < 0 || v >= N_NODES) ok = 0;
    }
    g_idx64 = ok;
}

__global__ void init_kernel() {
    int i = blockIdx.x * blockDim.x + threadIdx.x;
    if (i < N_NODES) g_deg[i] = 0;
    if (i < N_GRAPHS * 32) { g_gmax[i] = 0.0f; g_gsum[i] = 0.0f; }
    if (i < N_GRAPHS) g_cnt[i] = 0.0f;
}

__global__ void deg_kernel(const void* __restrict__ ei) {
    int e = blockIdx.x * blockDim.x + threadIdx.x;
    if (e >= N_EDGES) return;
    int d;
    if (g_idx64) d = (int)((const long long*)ei)[N_EDGES + e];
    else         d = ((const int*)ei)[N_EDGES + e];
    atomicAdd(&g_deg[d], 1);
}

// ---- hierarchical exclusive scan of g_deg -> g_off / g_cur / g_dinv --------

// Pass 1: per-block sums (block covers SCAN_CHUNK contiguous elements).
__global__ void blocksum_kernel() {
    __shared__ int sh[256];
    int base = blockIdx.x * SCAN_CHUNK + threadIdx.x;
    int s = 0;
#pragma unroll
    for (int i = 0; i < SCAN_CHUNK / 256; i++) {
        int idx = base + i * 256;
        if (idx < N_NODES) s += g_deg[idx];
    }
    sh[threadIdx.x] = s;
    __syncthreads();
#pragma unroll
    for (int off = 128; off > 0; off >>= 1) {
        if (threadIdx.x < off) sh[threadIdx.x] += sh[threadIdx.x + off];
        __syncthreads();
    }
    if (threadIdx.x == 0) g_blksum[blockIdx.x] = sh[0];
}

// Pass 2: scan the 98 block sums (one small block).
__global__ void scanblk_kernel() {
    __shared__ int sh[128];
    int tid = threadIdx.x;
    int v = (tid < SCAN_NBLK) ? g_blksum[tid] : 0;
    sh[tid] = v;
    __syncthreads();
#pragma unroll
    for (int off = 1; off < 128; off <<= 1) {
        int t = (tid >= off) ? sh[tid - off] : 0;
        __syncthreads();
        sh[tid] += t;
        __syncthreads();
    }
    if (tid < SCAN_NBLK) g_blkoff[tid] = sh[tid] - v;   // exclusive
    if (tid == 127) g_off[N_NODES] = sh[127];           // total = N_EDGES
}

// Pass 3: per-block local exclusive scan + write offsets/cursors/dinv.
// Each thread owns 8 contiguous elements.
__global__ void writeoff_kernel() {
    __shared__ int sh[256];
    const int tid = threadIdx.x;
    int base = blockIdx.x * SCAN_CHUNK + tid * 8;
    int local[8];
    int s = 0;
#pragma unroll
    for (int i = 0; i < 8; i++) {
        int idx = base + i;
        local[i] = (idx < N_NODES) ? g_deg[idx] : 0;
        s += local[i];
    }
    sh[tid] = s;
    __syncthreads();
#pragma unroll
    for (int off = 1; off < 256; off <<= 1) {
        int t = (tid >= off) ? sh[tid - off] : 0;
        __syncthreads();
        sh[tid] += t;
        __syncthreads();
    }
    int run = g_blkoff[blockIdx.x] + sh[tid] - s;   // global exclusive prefix
#pragma unroll
    for (int i = 0; i < 8; i++) {
        int idx = base + i;
        if (idx < N_NODES) {
            g_off[idx] = run;
            g_cur[idx] = run;
            g_dinv[idx] = rsqrtf((float)(local[i] + 1));
            run += local[i];
        }
    }
}

__global__ void fill_kernel(const void* __restrict__ ei) {
    int e = blockIdx.x * blockDim.x + threadIdx.x;
    if (e >= N_EDGES) return;
    int s, d;
    if (g_idx64) {
        const long long* p = (const long long*)ei;
        s = (int)p[e]; d = (int)p[N_EDGES + e];
    } else {
        const int* p = (const int*)ei;
        s = p[e]; d = p[N_EDGES + e];
    }
    int pos = atomicAdd(&g_cur[d], 1);
    g_csr[pos] = s;
}

// xs = x * dinv  (width 8, float4 granularity: 2 threads/node)
__global__ void xscale_kernel(const float* __restrict__ x) {
    int t = blockIdx.x * blockDim.x + threadIdx.x;
    if (t >= N_NODES * 2) return;
    int node = t >> 1;
    float dv = g_dinv[node];
    float4 v = *(const float4*)(x + (size_t)t * 4);
    v.x *= dv; v.y *= dv; v.z *= dv; v.w *= dv;
    *(float4*)(g_xs + (size_t)t * 4) = v;
}

// ---------------- layer kernels ---------------------------------------------

// Width-8 input aggregation: t0[d] = dinv[d] * (sum_s xs[s] + xs[d]).
// 8 threads per node, scalar floats (one 32B sector per edge).
__global__ void agg0_kernel() {
    int gid = blockIdx.x * blockDim.x + threadIdx.x;
    int node = gid >> 3;
    int lane = gid & 7;
    if (node >= N_NODES) return;
    float acc0 = g_xs[(size_t)node * 8 + lane];
    float acc1 = 0.0f;
    int e = g_off[node], e1 = g_off[node + 1];
    for (; e + 2 <= e1; e += 2) {
        int s0 = __ldg(&g_csr[e]);
        int s1 = __ldg(&g_csr[e + 1]);
        acc0 += __ldg(&g_xs[(size_t)s0 * 8 + lane]);
        acc1 += __ldg(&g_xs[(size_t)s1 * 8 + lane]);
    }
    if (e < e1) {
        int s0 = __ldg(&g_csr[e]);
        acc0 += __ldg(&g_xs[(size_t)s0 * 8 + lane]);
    }
    g_U[(size_t)node * 8 + lane] = (acc0 + acc1) * g_dinv[node];
}

// GEMM: out = in @ W  (optionally epilogue: tanh(.+b)*dinv for layer 0)
// EPI: 0 = none, 1 = tanh(+b)*dinv
template <int K, int NO, int EPI>
__global__ void gemm_kernel(const float* __restrict__ in, const float* __restrict__ W,
                            const float* __restrict__ b, float* __restrict__ out) {
    const int TPN = NO / 4;
    const int NPB = 256 / TPN;
    __shared__ float sW[K * NO];
    __shared__ float sIn[NPB * K];
    for (int i = threadIdx.x; i < K * NO; i += 256) sW[i] = W[i];
    int node0 = blockIdx.x * NPB;
    for (int i = threadIdx.x; i < NPB * K; i += 256) {
        int n = node0 + i / K;
        sIn[i] = (n < N_NODES) ? in[(size_t)n * K + (i % K)] : 0.0f;
    }
    __syncthreads();
    int node = node0 + threadIdx.x / TPN;
    int oc   = (threadIdx.x % TPN) * 4;
    if (node >= N_NODES) return;
    const float* r = sIn + (threadIdx.x / TPN) * K;
    float a0 = 0.f, a1 = 0.f, a2 = 0.f, a3 = 0.f;
#pragma unroll
    for (int k = 0; k < K; k++) {
        float xv = r[k];
        float4 w = *(const float4*)(sW + k * NO + oc);
        a0 += xv * w.x; a1 += xv * w.y; a2 += xv * w.z; a3 += xv * w.w;
    }
    float4 res;
    if (EPI == 1) {
        float dv = g_dinv[node];
        float4 bb = *(const float4*)(b + oc);
        res.x = tanhf(a0 + bb.x) * dv;
        res.y = tanhf(a1 + bb.y) * dv;
        res.z = tanhf(a2 + bb.z) * dv;
        res.w = tanhf(a3 + bb.w) * dv;
    } else {
        res = make_float4(a0, a1, a2, a3);
    }
    *(float4*)(out + (size_t)node * NO + oc) = res;
}

// Aggregation in output space + epilogue.
// out_next = relu(dinv*(sum u[s] + u[d]) + b)  [* dinv if !POOL]
// 16 threads/node, V = NO/16 floats per thread (4 for NO=64, 2 for NO=32).
template <int NO, bool POOL>
__global__ void agg_act_kernel(const float* __restrict__ u, const float* __restrict__ b,
                               float* __restrict__ out, const void* __restrict__ batch) {
    const int V = NO / 16;
    int gid  = blockIdx.x * blockDim.x + threadIdx.x;
    int node = gid >> 4;
    int lane = gid & 15;
    if (node >= N_NODES) return;
    const float* urow = u + (size_t)node * NO + lane * V;
    float acc0[V], acc1[V];
#pragma unroll
    for (int j = 0; j < V; j++) { acc0[j] = urow[j]; acc1[j] = 0.0f; }
    int e = g_off[node], e1 = g_off[node + 1];
    for (; e + 2 <= e1; e += 2) {
        int s0 = __ldg(&g_csr[e]);
        int s1 = __ldg(&g_csr[e + 1]);
        const float* p0 = u + (size_t)s0 * NO + lane * V;
        const float* p1 = u + (size_t)s1 * NO + lane * V;
#pragma unroll
        for (int j = 0; j < V; j++) { acc0[j] += __ldg(p0 + j); acc1[j] += __ldg(p1 + j); }
    }
    if (e < e1) {
        int s0 = __ldg(&g_csr[e]);
        const float* p0 = u + (size_t)s0 * NO + lane * V;
#pragma unroll
        for (int j = 0; j < V; j++) acc0[j] += __ldg(p0 + j);
    }
    float dv = g_dinv[node];
    float val[V];
#pragma unroll
    for (int j = 0; j < V; j++)
        val[j] = fmaxf(fmaf(dv, acc0[j] + acc1[j], b[lane * V + j]), 0.0f);
    if (!POOL) {
#pragma unroll
        for (int j = 0; j < V; j++)
            out[(size_t)node * NO + lane * V + j] = val[j] * dv;
    } else {
        int g;
        if (g_idx64) g = (int)((const long long*)batch)[node];
        else         g = ((const int*)batch)[node];
        int base = g * 32 + lane * V;
#pragma unroll
        for (int j = 0; j < V; j++) {
            atomicMax((int*)&g_gmax[base + j], __float_as_int(val[j]));
            atomicAdd(&g_gsum[base + j], val[j]);
        }
        if (lane == 0) atomicAdd(&g_cnt[g], 1.0f);
    }
}

__global__ void final_kernel(const float* __restrict__ Wout, const float* __restrict__ bout,
                             float* __restrict__ out) {
    int idx = blockIdx.x * blockDim.x + threadIdx.x;
    if (idx >= N_GRAPHS * 10) return;
    int g = idx / 10, o = idx % 10;
    float inv = 1.0f / fmaxf(g_cnt[g], 1.0f);
    float s = bout[o];
#pragma unroll
    for (int f = 0; f < 32; f++) s = fmaf(g_gmax[g * 32 + f], Wout[f * 10 + o], s);
#pragma unroll
    for (int f = 0; f < 32; f++) s = fmaf(g_gsum[g * 32 + f] * inv, Wout[(32 + f) * 10 + o], s);
    out[idx] = s;
}

// ---------------- launch -----------------------------------------------------

extern "C" void kernel_launch(void* const* d_in, const int* in_sizes, int n_in,
                              void* d_out, int out_size) {
    const float* x     = (const float*)d_in[0];
    const void*  ei    = d_in[1];
    const void*  batch = d_in[2];
    const float* W0 = (const float*)d_in[3];  const float* b0 = (const float*)d_in[4];
    const float* W1 = (const float*)d_in[5];  const float* b1 = (const float*)d_in[6];
    const float* W2 = (const float*)d_in[7];  const float* b2 = (const float*)d_in[8];
    const float* W3 = (const float*)d_in[9];  const float* b3 = (const float*)d_in[10];
    const float* Wout = (const float*)d_in[11];
    const float* bout = (const float*)d_in[12];
    float* out = (float*)d_out;

    float *S, *U;
    cudaGetSymbolAddress((void**)&S, g_S);
    cudaGetSymbolAddress((void**)&U, g_U);

    const int T = 256;
    const int NB_N  = (N_NODES + T - 1) / T;
    const int NB_E  = (N_EDGES + T - 1) / T;
    const int NB_N2 = (N_NODES * 2 + T - 1) / T;
    const int NB_N8 = (N_NODES * 8 + T - 1) / T;
    const int NB_N16 = (N_NODES * 16 + T - 1) / T;

    // graph prep
    detect_kernel<<<1, 1>>>(ei);
    init_kernel<<<NB_N, T>>>();
    deg_kernel<<<NB_E, T>>>(ei);
    blocksum_kernel<<<SCAN_NBLK, 256>>>();
    scanblk_kernel<<<1, 128>>>();
    writeoff_kernel<<<SCAN_NBLK, 256>>>();
    fill_kernel<<<NB_E, T>>>(ei);

    // Layer 0 (8 -> 64, tanh): aggregate in input space (width 8), then GEMM+act.
    xscale_kernel<<<NB_N2, T>>>(x);
    agg0_kernel<<<NB_N8, T>>>();
    gemm_kernel<8, 64, 1><<<(N_NODES + 15) / 16, T>>>(U, W0, b0, S);

    // Layer 1 (64 -> 64, relu): GEMM then aggregate (width 64).
    gemm_kernel<64, 64, 0><<<(N_NODES + 15) / 16, T>>>(S, W1, nullptr, U);
    agg_act_kernel<64, false><<<NB_N16, T>>>(U, b1, S, nullptr);

    // Layer 2 (64 -> 32, relu): GEMM then aggregate (width 32).
    gemm_kernel<64, 32, 0><<<(N_NODES + 31) / 32, T>>>(S, W2, nullptr, U);
    agg_act_kernel<32, false><<<NB_N16, T>>>(U, b2, S, nullptr);

    // Layer 3 (32 -> 32, relu): GEMM then aggregate + fused pooling.
    gemm_kernel<32, 32, 0><<<(N_NODES + 31) / 32, T>>>(S, W3, nullptr, U);
    agg_act_kernel<32, true><<<NB_N16, T>>>(U, b3, nullptr, batch);

    final_kernel<<<(N_GRAPHS * 10 + T - 1) / T, T>>>(Wout, bout, out);
}

// round 6
// speedup vs baseline: 1.9892x; 1.1711x over previous
#include <cuda_runtime.h>
#include <cuda_fp16.h>

#define N_NODES   200000
#define N_EDGES   3200000
#define N_GRAPHS  1024

#define SCAN_CHUNK 2048
#define SCAN_NBLK  ((N_NODES + SCAN_CHUNK - 1) / SCAN_CHUNK)   // 98

// ---------------- scratch (static device globals) ---------------------------
__device__ float  g_S[N_NODES * 64];    // scaled activations S = h * dinv (fp32)
__device__ __half g_Uh[N_NODES * 64];   // gemm outputs (messages, fp16)
__device__ float  g_T0[N_NODES * 8];    // layer-0 aggregated input
__device__ float  g_xs[N_NODES * 8];    // x * dinv
__device__ int    g_deg[N_NODES];
__device__ int    g_off[N_NODES + 1];   // CSR offsets (incoming edges by dst)
__device__ int    g_cur[N_NODES];       // fill cursors
__device__ int    g_csr[N_EDGES];       // src per slot
__device__ float  g_dinv[N_NODES];
__device__ int    g_blksum[SCAN_NBLK];
__device__ int    g_blkoff[SCAN_NBLK];
__device__ float  g_gmax[N_GRAPHS * 32];
__device__ float  g_gsum[N_GRAPHS * 32];
__device__ float  g_cnt[N_GRAPHS];
__device__ int    g_idx64;

// ---------------- prep kernels ----------------------------------------------

__global__ void detect_kernel(const void* __restrict__ ei) {
    const long long* p = (const long long*)ei;
    int ok = 1;
#pragma unroll
    for (int i = 0; i < 16; i++) {
        long long v = p[i];
        if (v < 0 || v >= N_NODES) ok = 0;
    }
    g_idx64 = ok;
}

__global__ void init_kernel() {
    int i = blockIdx.x * blockDim.x + threadIdx.x;
    if (i < N_NODES) g_deg[i] = 0;
    if (i < N_GRAPHS * 32) { g_gmax[i] = 0.0f; g_gsum[i] = 0.0f; }
    if (i < N_GRAPHS) g_cnt[i] = 0.0f;
}

__global__ void deg_kernel(const void* __restrict__ ei) {
    int e = blockIdx.x * blockDim.x + threadIdx.x;
    if (e >= N_EDGES) return;
    int d;
    if (g_idx64) d = (int)((const long long*)ei)[N_EDGES + e];
    else         d = ((const int*)ei)[N_EDGES + e];
    atomicAdd(&g_deg[d], 1);
}

// ---- hierarchical exclusive scan of g_deg -> g_off / g_cur / g_dinv --------

__global__ void blocksum_kernel() {
    __shared__ int sh[256];
    int base = blockIdx.x * SCAN_CHUNK + threadIdx.x;
    int s = 0;
#pragma unroll
    for (int i = 0; i < SCAN_CHUNK / 256; i++) {
        int idx = base + i * 256;
        if (idx < N_NODES) s += g_deg[idx];
    }
    sh[threadIdx.x] = s;
    __syncthreads();
#pragma unroll
    for (int off = 128; off > 0; off >>= 1) {
        if (threadIdx.x < off) sh[threadIdx.x] += sh[threadIdx.x + off];
        __syncthreads();
    }
    if (threadIdx.x == 0) g_blksum[blockIdx.x] = sh[0];
}

__global__ void scanblk_kernel() {
    __shared__ int sh[128];
    int tid = threadIdx.x;
    int v = (tid < SCAN_NBLK) ? g_blksum[tid] : 0;
    sh[tid] = v;
    __syncthreads();
#pragma unroll
    for (int off = 1; off < 128; off <<= 1) {
        int t = (tid >= off) ? sh[tid - off] : 0;
        __syncthreads();
        sh[tid] += t;
        __syncthreads();
    }
    if (tid < SCAN_NBLK) g_blkoff[tid] = sh[tid] - v;   // exclusive
    if (tid == 127) g_off[N_NODES] = sh[127];
}

__global__ void writeoff_kernel() {
    __shared__ int sh[256];
    const int tid = threadIdx.x;
    int base = blockIdx.x * SCAN_CHUNK + tid * 8;
    int local[8];
    int s = 0;
#pragma unroll
    for (int i = 0; i < 8; i++) {
        int idx = base + i;
        local[i] = (idx < N_NODES) ? g_deg[idx] : 0;
        s += local[i];
    }
    sh[tid] = s;
    __syncthreads();
#pragma unroll
    for (int off = 1; off < 256; off <<= 1) {
        int t = (tid >= off) ? sh[tid - off] : 0;
        __syncthreads();
        sh[tid] += t;
        __syncthreads();
    }
    int run = g_blkoff[blockIdx.x] + sh[tid] - s;
#pragma unroll
    for (int i = 0; i < 8; i++) {
        int idx = base + i;
        if (idx < N_NODES) {
            g_off[idx] = run;
            g_cur[idx] = run;
            g_dinv[idx] = rsqrtf((float)(local[i] + 1));
            run += local[i];
        }
    }
}

__global__ void fill_kernel(const void* __restrict__ ei) {
    int e = blockIdx.x * blockDim.x + threadIdx.x;
    if (e >= N_EDGES) return;
    int s, d;
    if (g_idx64) {
        const long long* p = (const long long*)ei;
        s = (int)p[e]; d = (int)p[N_EDGES + e];
    } else {
        const int* p = (const int*)ei;
        s = p[e]; d = p[N_EDGES + e];
    }
    int pos = atomicAdd(&g_cur[d], 1);
    g_csr[pos] = s;
}

// xs = x * dinv  (width 8, float4 granularity: 2 threads/node)
__global__ void xscale_kernel(const float* __restrict__ x) {
    int t = blockIdx.x * blockDim.x + threadIdx.x;
    if (t >= N_NODES * 2) return;
    int node = t >> 1;
    float dv = g_dinv[node];
    float4 v = *(const float4*)(x + (size_t)t * 4);
    v.x *= dv; v.y *= dv; v.z *= dv; v.w *= dv;
    *(float4*)(g_xs + (size_t)t * 4) = v;
}

// ---------------- layer kernels ---------------------------------------------

// Width-8 input aggregation: t0[d] = dinv[d] * (sum_s xs[s] + xs[d]).
__global__ void agg0_kernel() {
    int gid = blockIdx.x * blockDim.x + threadIdx.x;
    int node = gid >> 3;
    int lane = gid & 7;
    if (node >= N_NODES) return;
    float acc0 = g_xs[(size_t)node * 8 + lane];
    float acc1 = 0.0f;
    int e = g_off[node], e1 = g_off[node + 1];
    for (; e + 2 <= e1; e += 2) {
        int s0 = __ldg(&g_csr[e]);
        int s1 = __ldg(&g_csr[e + 1]);
        acc0 += __ldg(&g_xs[(size_t)s0 * 8 + lane]);
        acc1 += __ldg(&g_xs[(size_t)s1 * 8 + lane]);
    }
    if (e < e1) {
        int s0 = __ldg(&g_csr[e]);
        acc0 += __ldg(&g_xs[(size_t)s0 * 8 + lane]);
    }
    g_T0[(size_t)node * 8 + lane] = (acc0 + acc1) * g_dinv[node];
}

// GEMM: out = in @ W.
// EPI=1: tanh(.+b)*dinv, fp32 out (layer 0). EPI=0: raw, fp16 out (layers 1-3).
template <int K, int NO, int EPI>
__global__ void gemm_kernel(const float* __restrict__ in, const float* __restrict__ W,
                            const float* __restrict__ b, float* __restrict__ outf,
                            __half* __restrict__ outh) {
    const int TPN = NO / 4;
    const int NPB = 256 / TPN;
    __shared__ float sW[K * NO];
    __shared__ float sIn[NPB * K];
    for (int i = threadIdx.x; i < K * NO; i += 256) sW[i] = W[i];
    int node0 = blockIdx.x * NPB;
    for (int i = threadIdx.x; i < NPB * K; i += 256) {
        int n = node0 + i / K;
        sIn[i] = (n < N_NODES) ? in[(size_t)n * K + (i % K)] : 0.0f;
    }
    __syncthreads();
    int node = node0 + threadIdx.x / TPN;
    int oc   = (threadIdx.x % TPN) * 4;
    if (node >= N_NODES) return;
    const float* r = sIn + (threadIdx.x / TPN) * K;
    float a0 = 0.f, a1 = 0.f, a2 = 0.f, a3 = 0.f;
#pragma unroll
    for (int k = 0; k < K; k++) {
        float xv = r[k];
        float4 w = *(const float4*)(sW + k * NO + oc);
        a0 += xv * w.x; a1 += xv * w.y; a2 += xv * w.z; a3 += xv * w.w;
    }
    if (EPI == 1) {
        float dv = g_dinv[node];
        float4 bb = *(const float4*)(b + oc);
        float4 res;
        res.x = tanhf(a0 + bb.x) * dv;
        res.y = tanhf(a1 + bb.y) * dv;
        res.z = tanhf(a2 + bb.z) * dv;
        res.w = tanhf(a3 + bb.w) * dv;
        *(float4*)(outf + (size_t)node * NO + oc) = res;
    } else {
        __half2 h01 = __floats2half2_rn(a0, a1);
        __half2 h23 = __floats2half2_rn(a2, a3);
        uint2 st;
        st.x = *(unsigned int*)&h01;
        st.y = *(unsigned int*)&h23;
        *(uint2*)(outh + (size_t)node * NO + oc) = st;
    }
}

// Aggregation of fp16 messages + epilogue (fp32 accumulate).
// out_next = relu(dinv*(sum u[s] + u[d]) + b)  [* dinv if !POOL]
// 16 threads/node, V = NO/16 halves per thread (4 for NO=64, 2 for NO=32).
template <int NO, bool POOL>
__global__ void agg_act_kernel(const __half* __restrict__ u, const float* __restrict__ b,
                               float* __restrict__ out, const void* __restrict__ batch) {
    const int V = NO / 16;       // 4 or 2
    const int H2 = V / 2;        // half2 count: 2 or 1
    int gid  = blockIdx.x * blockDim.x + threadIdx.x;
    int node = gid >> 4;
    int lane = gid & 15;
    if (node >= N_NODES) return;
    float acc0[V], acc1[V];
    {
        const __half2* p = (const __half2*)(u + (size_t)node * NO + lane * V);
#pragma unroll
        for (int j = 0; j < H2; j++) {
            float2 f = __half22float2(__ldg(p + j));
            acc0[2 * j] = f.x; acc0[2 * j + 1] = f.y;
            acc1[2 * j] = 0.0f; acc1[2 * j + 1] = 0.0f;
        }
    }
    int e = g_off[node], e1 = g_off[node + 1];
    for (; e + 2 <= e1; e += 2) {
        int s0 = __ldg(&g_csr[e]);
        int s1 = __ldg(&g_csr[e + 1]);
        const __half2* p0 = (const __half2*)(u + (size_t)s0 * NO + lane * V);
        const __half2* p1 = (const __half2*)(u + (size_t)s1 * NO + lane * V);
#pragma unroll
        for (int j = 0; j < H2; j++) {
            float2 f0 = __half22float2(__ldg(p0 + j));
            float2 f1 = __half22float2(__ldg(p1 + j));
            acc0[2 * j] += f0.x; acc0[2 * j + 1] += f0.y;
            acc1[2 * j] += f1.x; acc1[2 * j + 1] += f1.y;
        }
    }
    if (e < e1) {
        int s0 = __ldg(&g_csr[e]);
        const __half2* p0 = (const __half2*)(u + (size_t)s0 * NO + lane * V);
#pragma unroll
        for (int j = 0; j < H2; j++) {
            float2 f0 = __half22float2(__ldg(p0 + j));
            acc0[2 * j] += f0.x; acc0[2 * j + 1] += f0.y;
        }
    }
    float dv = g_dinv[node];
    float val[V];
#pragma unroll
    for (int j = 0; j < V; j++)
        val[j] = fmaxf(fmaf(dv, acc0[j] + acc1[j], b[lane * V + j]), 0.0f);
    if (!POOL) {
#pragma unroll
        for (int j = 0; j < V; j++)
            out[(size_t)node * NO + lane * V + j] = val[j] * dv;
    } else {
        int g;
        if (g_idx64) g = (int)((const long long*)batch)[node];
        else         g = ((const int*)batch)[node];
        int base = g * 32 + lane * V;
#pragma unroll
        for (int j = 0; j < V; j++) {
            atomicMax((int*)&g_gmax[base + j], __float_as_int(val[j]));
            atomicAdd(&g_gsum[base + j], val[j]);
        }
        if (lane == 0) atomicAdd(&g_cnt[g], 1.0f);
    }
}

__global__ void final_kernel(const float* __restrict__ Wout, const float* __restrict__ bout,
                             float* __restrict__ out) {
    int idx = blockIdx.x * blockDim.x + threadIdx.x;
    if (idx >= N_GRAPHS * 10) return;
    int g = idx / 10, o = idx % 10;
    float inv = 1.0f / fmaxf(g_cnt[g], 1.0f);
    float s = bout[o];
#pragma unroll
    for (int f = 0; f < 32; f++) s = fmaf(g_gmax[g * 32 + f], Wout[f * 10 + o], s);
#pragma unroll
    for (int f = 0; f < 32; f++) s = fmaf(g_gsum[g * 32 + f] * inv, Wout[(32 + f) * 10 + o], s);
    out[idx] = s;
}

// ---------------- launch -----------------------------------------------------

extern "C" void kernel_launch(void* const* d_in, const int* in_sizes, int n_in,
                              void* d_out, int out_size) {
    const float* x     = (const float*)d_in[0];
    const void*  ei    = d_in[1];
    const void*  batch = d_in[2];
    const float* W0 = (const float*)d_in[3];  const float* b0 = (const float*)d_in[4];
    const float* W1 = (const float*)d_in[5];  const float* b1 = (const float*)d_in[6];
    const float* W2 = (const float*)d_in[7];  const float* b2 = (const float*)d_in[8];
    const float* W3 = (const float*)d_in[9];  const float* b3 = (const float*)d_in[10];
    const float* Wout = (const float*)d_in[11];
    const float* bout = (const float*)d_in[12];
    float* out = (float*)d_out;

    float *S, *T0;
    __half *Uh;
    cudaGetSymbolAddress((void**)&S, g_S);
    cudaGetSymbolAddress((void**)&T0, g_T0);
    cudaGetSymbolAddress((void**)&Uh, g_Uh);

    const int T = 256;
    const int NB_N  = (N_NODES + T - 1) / T;
    const int NB_E  = (N_EDGES + T - 1) / T;
    const int NB_N2 = (N_NODES * 2 + T - 1) / T;
    const int NB_N8 = (N_NODES * 8 + T - 1) / T;
    const int NB_N16 = (N_NODES * 16 + T - 1) / T;

    // graph prep
    detect_kernel<<<1, 1>>>(ei);
    init_kernel<<<NB_N, T>>>();
    deg_kernel<<<NB_E, T>>>(ei);
    blocksum_kernel<<<SCAN_NBLK, 256>>>();
    scanblk_kernel<<<1, 128>>>();
    writeoff_kernel<<<SCAN_NBLK, 256>>>();
    fill_kernel<<<NB_E, T>>>(ei);

    // Layer 0 (8 -> 64, tanh): aggregate in input space (width 8), then GEMM+act.
    xscale_kernel<<<NB_N2, T>>>(x);
    agg0_kernel<<<NB_N8, T>>>();
    gemm_kernel<8, 64, 1><<<(N_NODES + 15) / 16, T>>>(T0, W0, b0, S, nullptr);

    // Layer 1 (64 -> 64, relu): GEMM (fp16 out) then aggregate.
    gemm_kernel<64, 64, 0><<<(N_NODES + 15) / 16, T>>>(S, W1, nullptr, nullptr, Uh);
    agg_act_kernel<64, false><<<NB_N16, T>>>(Uh, b1, S, nullptr);

    // Layer 2 (64 -> 32, relu).
    gemm_kernel<64, 32, 0><<<(N_NODES + 31) / 32, T>>>(S, W2, nullptr, nullptr, Uh);
    agg_act_kernel<32, false><<<NB_N16, T>>>(Uh, b2, S, nullptr);

    // Layer 3 (32 -> 32, relu) + fused pooling.
    gemm_kernel<32, 32, 0><<<(N_NODES + 31) / 32, T>>>(S, W3, nullptr, nullptr, Uh);
    agg_act_kernel<32, true><<<NB_N16, T>>>(Uh, b3, nullptr, batch);

    final_kernel<<<(N_GRAPHS * 10 + T - 1) / T, T>>>(Wout, bout, out);
}